// round 1
// baseline (speedup 1.0000x reference)
#include <cuda_runtime.h>
#include <cuda_bf16.h>

// Segment-mean over sorted segment_ids.
// feats: [N, D] fp32 (D=128 in this problem, assumed divisible by 4)
// segment_ids: [N] int32, sorted ascending, values in [0, S)
// out: [S, D] fp32 = sum of rows in segment / max(count, 1)
//
// Strategy: sorted ids => each segment is a contiguous row range.
// One CTA per segment; boundaries via binary search (L2-resident id array).
// 32 threads * float4 cover one 512B row; 4 row-groups per 128-thread CTA;
// unrolled stride-4 row loop for memory-level parallelism. No atomics.

__device__ __forceinline__ int lower_bound_dev(const int* __restrict__ a, int n, int key) {
    int lo = 0, hi = n;
    while (lo < hi) {
        int mid = (lo + hi) >> 1;
        if (__ldg(a + mid) < key) lo = mid + 1;
        else hi = mid;
    }
    return lo;
}

__global__ void __launch_bounds__(128)
segmean_kernel(const float4* __restrict__ feats4,   // [N, D/4]
               const int* __restrict__ seg,          // [N]
               int N, int D4,                        // D4 = D/4
               float4* __restrict__ out4)            // [S, D/4]
{
    const int s   = blockIdx.x;
    const int tid = threadIdx.x;

    __shared__ int sh_range[2];
    if (tid == 0) {
        sh_range[0] = lower_bound_dev(seg, N, s);
        sh_range[1] = lower_bound_dev(seg, N, s + 1);
    }
    __syncthreads();
    const int start = sh_range[0];
    const int end   = sh_range[1];
    const int count = end - start;

    // threads-per-row = D4 (32 for D=128); row-groups = blockDim.x / D4 (4)
    const int tpr_groups = blockDim.x / D4;   // 4
    const int col  = tid % D4;                // float4 column within row
    const int rgrp = tid / D4;                // which row-group

    float4 acc = make_float4(0.f, 0.f, 0.f, 0.f);

    // Stride over rows in this segment; unroll for outstanding loads.
    long long base = (long long)start * D4 + col;
    int r = start + rgrp;
    #pragma unroll 4
    for (; r < end; r += tpr_groups) {
        float4 v = __ldg(feats4 + (long long)r * D4 + col);
        acc.x += v.x; acc.y += v.y; acc.z += v.z; acc.w += v.w;
    }
    (void)base;

    // Reduce across row-groups through shared memory.
    __shared__ float4 sh[128];
    sh[tid] = acc;
    __syncthreads();

    if (rgrp == 0) {
        float4 a = sh[col];
        for (int g = 1; g < tpr_groups; ++g) {
            float4 b = sh[g * D4 + col];
            a.x += b.x; a.y += b.y; a.z += b.z; a.w += b.w;
        }
        const float inv = 1.0f / (float)max(count, 1);
        a.x *= inv; a.y *= inv; a.z *= inv; a.w *= inv;
        out4[(long long)s * D4 + col] = a;
    }
}

extern "C" void kernel_launch(void* const* d_in, const int* in_sizes, int n_in,
                              void* d_out, int out_size) {
    const float* feats = (const float*)d_in[0];
    const int*   seg   = (const int*)d_in[1];

    const int N  = in_sizes[1];          // number of rows (len of segment_ids)
    const int D  = in_sizes[0] / N;      // feature dim (128)
    const int D4 = D >> 2;
    const int S  = out_size / D;         // number of segments

    segmean_kernel<<<S, 128>>>((const float4*)feats, seg, N, D4, (float4*)d_out);
}

// round 3
// speedup vs baseline: 1.1640x; 1.1640x over previous
#include <cuda_runtime.h>
#include <cuda_bf16.h>

// Segment-mean over sorted segment_ids, two-kernel plan:
//  K1 build_starts: one pass over ids -> starts[S+1] (starts[s] = first row
//     index with seg >= s). Kills the per-CTA binary-search prologue that was
//     costing ~20% of runtime (serialized thread-0 searches under barrier).
//  K2 segmean: one CTA per segment, boundaries are two broadcast L2 loads,
//     then a clean coalesced float4 streaming sum. No atomics anywhere.

#define MAX_SEGMENTS (1 << 22)             // 4M segments max; S=16384 here
__device__ int g_starts[MAX_SEGMENTS + 1]; // scratch (alloc-free rule)

__global__ void build_starts(const int* __restrict__ seg, int N, int S,
                             int* __restrict__ starts) {
    int i = blockIdx.x * blockDim.x + threadIdx.x;
    if (i >= N) return;
    int cur = __ldg(seg + i);
    if (i == 0) {
        // all s <= seg[0] start at row 0
        for (int s = 0; s <= cur; ++s) starts[s] = 0;
    } else {
        int prev = __ldg(seg + i - 1);
        if (prev != cur) {
            for (int s = prev + 1; s <= cur; ++s) starts[s] = i;
        }
    }
    if (i == N - 1) {
        // all s > seg[N-1] (and the sentinel S) start at N
        for (int s = cur + 1; s <= S; ++s) starts[s] = N;
    }
}

__global__ void __launch_bounds__(128)
segmean_kernel(const float4* __restrict__ feats4,   // [N, D/4]
               const int* __restrict__ starts,       // [S+1]
               int D4,                               // D/4 (=32)
               float4* __restrict__ out4)            // [S, D/4]
{
    const int s   = blockIdx.x;
    const int tid = threadIdx.x;

    // Broadcast loads — L2 hits after first wave; no sync, no search.
    const int start = __ldg(starts + s);
    const int end   = __ldg(starts + s + 1);
    const int count = end - start;

    const int tpr_groups = blockDim.x / D4;   // 4 row-groups (one warp each)
    const int col  = tid % D4;                // float4 column within row
    const int rgrp = tid / D4;                // row-group = warp id

    float4 acc = make_float4(0.f, 0.f, 0.f, 0.f);

    #pragma unroll 4
    for (int r = start + rgrp; r < end; r += tpr_groups) {
        float4 v = __ldg(feats4 + (long long)r * D4 + col);
        acc.x += v.x; acc.y += v.y; acc.z += v.z; acc.w += v.w;
    }

    // Reduce the 4 row-groups through shared memory.
    __shared__ float4 sh[128];
    sh[tid] = acc;
    __syncthreads();

    if (rgrp == 0) {
        float4 a = sh[col];
        #pragma unroll
        for (int g = 1; g < 4; ++g) {
            float4 b = sh[g * D4 + col];
            a.x += b.x; a.y += b.y; a.z += b.z; a.w += b.w;
        }
        const float inv = 1.0f / (float)max(count, 1);
        a.x *= inv; a.y *= inv; a.z *= inv; a.w *= inv;
        out4[(long long)s * D4 + col] = a;
    }
}

extern "C" void kernel_launch(void* const* d_in, const int* in_sizes, int n_in,
                              void* d_out, int out_size) {
    const float* feats = (const float*)d_in[0];
    const int*   seg   = (const int*)d_in[1];

    const int N  = in_sizes[1];          // rows (len of segment_ids)
    const int D  = in_sizes[0] / N;      // feature dim (128)
    const int D4 = D >> 2;
    const int S  = out_size / D;         // number of segments

    int* starts = nullptr;
    cudaGetSymbolAddress((void**)&starts, g_starts);

    build_starts<<<(N + 255) / 256, 256>>>(seg, N, S, starts);
    segmean_kernel<<<S, 128>>>((const float4*)feats, starts, D4, (float4*)d_out);
}

// round 8
// speedup vs baseline: 1.2435x; 1.0682x over previous
#include <cuda_runtime.h>
#include <cuda_bf16.h>

// Segment-mean over sorted segment_ids, two-kernel plan:
//  K1 build_starts_vec4: vectorized boundary scan (int4: 4 ids/thread) ->
//     starts[S+1]. Previous scalar version was latency-bound at ~8us for 8MB;
//     this one has 1/4 the threads and 128-bit loads -> ~2-3us.
//  K2 segmean: one CTA per segment, boundaries are two broadcast L2 loads,
//     coalesced float4 streaming sum with __ldcs (evict-first: the 1GB feat
//     stream can never fit L2; keep L2 ways for ids/starts/output).

#define MAX_SEGMENTS (1 << 22)
__device__ int g_starts[MAX_SEGMENTS + 1];

__global__ void build_starts_vec4(const int* __restrict__ seg, int N, int S,
                                  int* __restrict__ starts) {
    const int t  = blockIdx.x * blockDim.x + threadIdx.x;
    const int e0 = t * 4;                 // first element this thread owns
    if (e0 >= N) return;

    int v0, v1, v2, v3;
    if (e0 + 3 < N) {
        int4 v = __ldg((const int4*)(seg + e0));
        v0 = v.x; v1 = v.y; v2 = v.z; v3 = v.w;
    } else {                              // partial tail quad (generic N)
        v0 = __ldg(seg + e0);
        v1 = (e0 + 1 < N) ? __ldg(seg + e0 + 1) : v0;
        v2 = (e0 + 2 < N) ? __ldg(seg + e0 + 2) : v1;
        v3 = (e0 + 3 < N) ? __ldg(seg + e0 + 3) : v2;
    }

    // Boundary at position j (between j-1 and j) for j in [e0, e0+4) ∩ [1, N)
    if (e0 == 0) {
        for (int s = 0; s <= v0; ++s) starts[s] = 0;   // prefix
    } else {
        int pv = __ldg(seg + e0 - 1);
        if (pv != v0) for (int s = pv + 1; s <= v0; ++s) starts[s] = e0;
    }
    if (e0 + 1 < N && v0 != v1) for (int s = v0 + 1; s <= v1; ++s) starts[s] = e0 + 1;
    if (e0 + 2 < N && v1 != v2) for (int s = v1 + 1; s <= v2; ++s) starts[s] = e0 + 2;
    if (e0 + 3 < N && v2 != v3) for (int s = v2 + 1; s <= v3; ++s) starts[s] = e0 + 3;

    // Suffix fill by the thread owning element N-1
    if (e0 <= N - 1 && N - 1 < e0 + 4) {
        int last = (N - 1 == e0) ? v0 : (N - 1 == e0 + 1) ? v1
                 : (N - 1 == e0 + 2) ? v2 : v3;
        for (int s = last + 1; s <= S; ++s) starts[s] = N;
    }
}

__global__ void __launch_bounds__(128)
segmean_kernel(const float4* __restrict__ feats4,   // [N, D/4]
               const int* __restrict__ starts,       // [S+1]
               int D4,                               // D/4 (=32)
               float4* __restrict__ out4)            // [S, D/4]
{
    const int s   = blockIdx.x;
    const int tid = threadIdx.x;

    const int start = __ldg(starts + s);
    const int end   = __ldg(starts + s + 1);
    const int count = end - start;

    const int tpr_groups = blockDim.x / D4;   // 4 row-groups (one warp each)
    const int col  = tid % D4;
    const int rgrp = tid / D4;

    float4 acc = make_float4(0.f, 0.f, 0.f, 0.f);

    #pragma unroll 4
    for (int r = start + rgrp; r < end; r += tpr_groups) {
        float4 v = __ldcs(feats4 + (long long)r * D4 + col);  // evict-first
        acc.x += v.x; acc.y += v.y; acc.z += v.z; acc.w += v.w;
    }

    __shared__ float4 sh[128];
    sh[tid] = acc;
    __syncthreads();

    if (rgrp == 0) {
        float4 a = sh[col];
        #pragma unroll
        for (int g = 1; g < 4; ++g) {
            float4 b = sh[g * D4 + col];
            a.x += b.x; a.y += b.y; a.z += b.z; a.w += b.w;
        }
        const float inv = 1.0f / (float)max(count, 1);
        a.x *= inv; a.y *= inv; a.z *= inv; a.w *= inv;
        out4[(long long)s * D4 + col] = a;
    }
}

extern "C" void kernel_launch(void* const* d_in, const int* in_sizes, int n_in,
                              void* d_out, int out_size) {
    const float* feats = (const float*)d_in[0];
    const int*   seg   = (const int*)d_in[1];

    const int N  = in_sizes[1];
    const int D  = in_sizes[0] / N;      // 128
    const int D4 = D >> 2;
    const int S  = out_size / D;

    int* starts = nullptr;
    cudaGetSymbolAddress((void**)&starts, g_starts);

    const int quads = (N + 3) / 4;
    build_starts_vec4<<<(quads + 255) / 256, 256>>>(seg, N, S, starts);
    segmean_kernel<<<S, 128>>>((const float4*)feats, starts, D4, (float4*)d_out);
}

// round 9
// speedup vs baseline: 1.3611x; 1.0946x over previous
#include <cuda_runtime.h>
#include <cuda_bf16.h>

// Segment-mean over sorted segment_ids, two-kernel plan (near HBM ceiling):
//  K1 build_starts_vec4: int4-vectorized boundary scan -> starts[S+1] (~2us).
//  K2 segmean: one CTA per segment, 4 warps x float4 columns, manually
//     4-deep pipelined __ldcs stream (evict-first), __stcs output stores.
//  Measured R8: 161.8us total @ 6.36 TB/s (~near LTS/HBM practical cap).

#define MAX_SEGMENTS (1 << 22)
__device__ int g_starts[MAX_SEGMENTS + 1];

__global__ void build_starts_vec4(const int* __restrict__ seg, int N, int S,
                                  int* __restrict__ starts) {
    const int t  = blockIdx.x * blockDim.x + threadIdx.x;
    const int e0 = t * 4;
    if (e0 >= N) return;

    int v0, v1, v2, v3;
    if (e0 + 3 < N) {
        int4 v = __ldg((const int4*)(seg + e0));
        v0 = v.x; v1 = v.y; v2 = v.z; v3 = v.w;
    } else {
        v0 = __ldg(seg + e0);
        v1 = (e0 + 1 < N) ? __ldg(seg + e0 + 1) : v0;
        v2 = (e0 + 2 < N) ? __ldg(seg + e0 + 2) : v1;
        v3 = (e0 + 3 < N) ? __ldg(seg + e0 + 3) : v2;
    }

    if (e0 == 0) {
        for (int s = 0; s <= v0; ++s) starts[s] = 0;
    } else {
        int pv = __ldg(seg + e0 - 1);
        if (pv != v0) for (int s = pv + 1; s <= v0; ++s) starts[s] = e0;
    }
    if (e0 + 1 < N && v0 != v1) for (int s = v0 + 1; s <= v1; ++s) starts[s] = e0 + 1;
    if (e0 + 2 < N && v1 != v2) for (int s = v1 + 1; s <= v2; ++s) starts[s] = e0 + 2;
    if (e0 + 3 < N && v2 != v3) for (int s = v2 + 1; s <= v3; ++s) starts[s] = e0 + 3;

    if (e0 <= N - 1 && N - 1 < e0 + 4) {
        int last = (N - 1 == e0) ? v0 : (N - 1 == e0 + 1) ? v1
                 : (N - 1 == e0 + 2) ? v2 : v3;
        for (int s = last + 1; s <= S; ++s) starts[s] = N;
    }
}

__global__ void __launch_bounds__(128)
segmean_kernel(const float4* __restrict__ feats4,   // [N, D/4]
               const int* __restrict__ starts,       // [S+1]
               int D4,                               // D/4 (=32)
               float4* __restrict__ out4)            // [S, D/4]
{
    const int s   = blockIdx.x;
    const int tid = threadIdx.x;

    const int start = __ldg(starts + s);
    const int end   = __ldg(starts + s + 1);
    const int count = end - start;

    const int step = blockDim.x / D4;         // 4 row-groups (one warp each)
    const int col  = tid % D4;
    const int rgrp = tid / D4;

    float4 acc = make_float4(0.f, 0.f, 0.f, 0.f);

    int r = start + rgrp;
    const long long colL = col;

    // Main loop: 4 rows per warp-iteration, loads issued back-to-back so
    // 4 LDG.128 are outstanding before the first FADD consumes one.
    for (; r + 3 * step < end; r += 4 * step) {
        float4 a0 = __ldcs(feats4 + (long long)(r           ) * D4 + colL);
        float4 a1 = __ldcs(feats4 + (long long)(r +     step) * D4 + colL);
        float4 a2 = __ldcs(feats4 + (long long)(r + 2 * step) * D4 + colL);
        float4 a3 = __ldcs(feats4 + (long long)(r + 3 * step) * D4 + colL);
        acc.x += a0.x; acc.y += a0.y; acc.z += a0.z; acc.w += a0.w;
        acc.x += a1.x; acc.y += a1.y; acc.z += a1.z; acc.w += a1.w;
        acc.x += a2.x; acc.y += a2.y; acc.z += a2.z; acc.w += a2.w;
        acc.x += a3.x; acc.y += a3.y; acc.z += a3.z; acc.w += a3.w;
    }
    // Tail
    for (; r < end; r += step) {
        float4 v = __ldcs(feats4 + (long long)r * D4 + colL);
        acc.x += v.x; acc.y += v.y; acc.z += v.z; acc.w += v.w;
    }

    __shared__ float4 sh[128];
    sh[tid] = acc;
    __syncthreads();

    if (rgrp == 0) {
        float4 a = sh[col];
        #pragma unroll
        for (int g = 1; g < 4; ++g) {
            float4 b = sh[g * D4 + col];
            a.x += b.x; a.y += b.y; a.z += b.z; a.w += b.w;
        }
        const float inv = 1.0f / (float)max(count, 1);
        a.x *= inv; a.y *= inv; a.z *= inv; a.w *= inv;
        __stcs(out4 + (long long)s * D4 + col, a);   // streaming store
    }
}

extern "C" void kernel_launch(void* const* d_in, const int* in_sizes, int n_in,
                              void* d_out, int out_size) {
    const float* feats = (const float*)d_in[0];
    const int*   seg   = (const int*)d_in[1];

    const int N  = in_sizes[1];
    const int D  = in_sizes[0] / N;      // 128
    const int D4 = D >> 2;
    const int S  = out_size / D;

    int* starts = nullptr;
    cudaGetSymbolAddress((void**)&starts, g_starts);

    const int quads = (N + 3) / 4;
    build_starts_vec4<<<(quads + 255) / 256, 256>>>(seg, N, S, starts);
    segmean_kernel<<<S, 128>>>((const float4*)feats, starts, D4, (float4*)d_out);
}